// round 3
// baseline (speedup 1.0000x reference)
#include <cuda_runtime.h>
#include <math.h>

#define NN   50000      // nodes
#define NE   800000     // edges
#define IND  50         // input dim
#define HID  256        // hidden
#define NC   121        // classes
#define XP   64         // padded x / mean row stride
#define PRLS 384        // combined [p(0..127) | r(128..255) | l2(256..383)] row stride

// ---------------- scratch (device globals) ----------------------------------
__device__ __align__(16) float g_xpad[(size_t)NN * XP];
__device__ __align__(16) float g_mean[(size_t)NN * XP];    // mean of x over in-neighbors
__device__ __align__(16) float g_h   [(size_t)NN * HID];
__device__ __align__(16) float g_prl [(size_t)NN * PRLS];
__device__ int g_cnt[NN];          // dst histogram
__device__ int g_off[NN + 1];      // CSR offsets
__device__ int g_cur[NN];          // fill cursors
__device__ int g_adj[NE];          // src ids grouped by dst

// ---------------- zero histogram ---------------------------------------------
__global__ __launch_bounds__(1024) void zero_cnt_kernel() {
    int i = blockIdx.x * 1024 + threadIdx.x;
    if (i < NN) g_cnt[i] = 0;
}

// ---------------- pad x into [NN, 64] -----------------------------------------
__global__ __launch_bounds__(256) void pad_x_kernel(const float* __restrict__ x) {
    int t = blockIdx.x * blockDim.x + threadIdx.x;
    if (t >= NN * XP) return;
    int row = t >> 6, c = t & 63;
    g_xpad[t] = (c < IND) ? x[row * IND + c] : 0.f;
}

// ---------------- CSR build: histogram ----------------------------------------
__global__ __launch_bounds__(256) void hist_kernel(const int* __restrict__ ei) {
    int e = blockIdx.x * blockDim.x + threadIdx.x;
    if (e < NE) atomicAdd(&g_cnt[ei[NE + e]], 1);
}

// ---------------- CSR build: exclusive scan (single block) --------------------
__global__ __launch_bounds__(1024) void scan_kernel() {
    __shared__ int sp[1024];
    const int CH = (NN + 1023) / 1024;   // 49
    int t = threadIdx.x;
    int base = t * CH;
    int sum = 0;
    for (int i = 0; i < CH; i++) {
        int idx = base + i;
        if (idx < NN) sum += g_cnt[idx];
    }
    sp[t] = sum;
    __syncthreads();
    for (int d = 1; d < 1024; d <<= 1) {
        int v = (t >= d) ? sp[t - d] : 0;
        __syncthreads();
        sp[t] += v;
        __syncthreads();
    }
    int run = (t == 0) ? 0 : sp[t - 1];
    for (int i = 0; i < CH; i++) {
        int idx = base + i;
        if (idx < NN) { g_off[idx] = run; g_cur[idx] = run; run += g_cnt[idx]; }
    }
    if (t == 0) g_off[NN] = NE;
}

// ---------------- CSR build: fill adjacency ------------------------------------
__global__ __launch_bounds__(256) void fill_kernel(const int* __restrict__ ei) {
    int e = blockIdx.x * blockDim.x + threadIdx.x;
    if (e >= NE) return;
    int pos = atomicAdd(&g_cur[ei[NE + e]], 1);
    g_adj[pos] = ei[e];
}

// ---------------- gather 1: mean of x over neighbors ---------------------------
// half-warp (16 lanes) per node; lanes 0..12 hold 13 float4 accumulators (52 cols)
__global__ __launch_bounds__(256) void gather1_kernel() {
    int t = blockIdx.x * blockDim.x + threadIdx.x;
    int n = t >> 4;
    if (n >= NN) return;
    int l = t & 15;
    int b = g_off[n], e2 = g_off[n + 1];
    float inv = 1.f / fmaxf((float)(e2 - b), 1.f);
    float4 a = make_float4(0.f, 0.f, 0.f, 0.f);
    int i = b;
    for (; i + 1 < e2; i += 2) {
        int s0 = g_adj[i], s1 = g_adj[i + 1];
        if (l < 13) {
            float4 v0 = *(const float4*)(g_xpad + (size_t)s0 * XP + l * 4);
            float4 v1 = *(const float4*)(g_xpad + (size_t)s1 * XP + l * 4);
            a.x += v0.x + v1.x; a.y += v0.y + v1.y;
            a.z += v0.z + v1.z; a.w += v0.w + v1.w;
        }
    }
    if (i < e2) {
        int s0 = g_adj[i];
        if (l < 13) {
            float4 v0 = *(const float4*)(g_xpad + (size_t)s0 * XP + l * 4);
            a.x += v0.x; a.y += v0.y; a.z += v0.z; a.w += v0.w;
        }
    }
    if (l < 13) {
        a.x *= inv; a.y *= inv; a.z *= inv; a.w *= inv;
        *(float4*)(g_mean + (size_t)n * XP + l * 4) = a;
    }
}

// ---------------- layer-1 fused GEMM + L2-normalize + ELU ----------------------
// 256 threads (one per output column), 32 rows per block
__global__ __launch_bounds__(256) void gemm1_kernel(
    const float* __restrict__ x,
    const float* __restrict__ w1l, const float* __restrict__ b1,
    const float* __restrict__ w1r,
    const float* __restrict__ wl1, const float* __restrict__ bl1)
{
    __shared__ __align__(16) float sm[32][64];
    __shared__ __align__(16) float sx[32][64];
    __shared__ float spart[32][8];

    int j = threadIdx.x;
    int row0 = blockIdx.x * 32;

    for (int i = j; i < 32 * 52; i += 256) {
        int r = i / 52, c = i % 52;
        int row = row0 + r;
        bool ok = (row < NN);
        sm[r][c] = ok ? g_mean[(size_t)row * XP + c] : 0.f;
        sx[r][c] = (ok && c < IND) ? x[(size_t)row * IND + c] : 0.f;
    }
    __syncthreads();

    float acc[32], lin[32];
    float bj = b1[j], blj = bl1[j];
#pragma unroll
    for (int r = 0; r < 32; r++) { acc[r] = bj; lin[r] = blj; }

    for (int k = 0; k < 48; k += 4) {
        float wa0 = w1l[(k+0)*HID + j], wa1 = w1l[(k+1)*HID + j];
        float wa2 = w1l[(k+2)*HID + j], wa3 = w1l[(k+3)*HID + j];
        float wb0 = w1r[(k+0)*HID + j], wb1 = w1r[(k+1)*HID + j];
        float wb2 = w1r[(k+2)*HID + j], wb3 = w1r[(k+3)*HID + j];
        float wc0 = wl1[(k+0)*HID + j], wc1 = wl1[(k+1)*HID + j];
        float wc2 = wl1[(k+2)*HID + j], wc3 = wl1[(k+3)*HID + j];
#pragma unroll
        for (int r = 0; r < 32; r++) {
            float4 m  = *(const float4*)&sm[r][k];
            float4 xv = *(const float4*)&sx[r][k];
            acc[r] += m.x*wa0 + m.y*wa1 + m.z*wa2 + m.w*wa3
                    + xv.x*wb0 + xv.y*wb1 + xv.z*wb2 + xv.w*wb3;
            lin[r] += xv.x*wc0 + xv.y*wc1 + xv.z*wc2 + xv.w*wc3;
        }
    }
    for (int k = 48; k < 50; k++) {
        float wa = w1l[k*HID + j], wb = w1r[k*HID + j], wc = wl1[k*HID + j];
#pragma unroll
        for (int r = 0; r < 32; r++) {
            acc[r] += sm[r][k] * wa + sx[r][k] * wb;
            lin[r] += sx[r][k] * wc;
        }
    }

    int lane = j & 31, warp = j >> 5;
#pragma unroll
    for (int r = 0; r < 32; r++) {
        float v = acc[r] * acc[r];
#pragma unroll
        for (int o = 16; o; o >>= 1) v += __shfl_xor_sync(0xffffffffu, v, o);
        if (lane == 0) spart[r][warp] = v;
    }
    __syncthreads();
#pragma unroll
    for (int r = 0; r < 32; r++) {
        if (row0 + r >= NN) break;
        float s = 0.f;
#pragma unroll
        for (int w = 0; w < 8; w++) s += spart[r][w];
        float inv = 1.f / fmaxf(sqrtf(s), 1e-12f);
        float z = acc[r] * inv + lin[r];
        g_h[(size_t)(row0 + r) * HID + j] = (z > 0.f) ? z : expm1f(z);
    }
}

// ---------------- layer-2 GEMM: [p | r | l2] = h @ [w2_l | w2_r | wl2] ---------
// 384 threads (one per combined column), 32 rows per block
__global__ __launch_bounds__(384) void gemm2_kernel(
    const float* __restrict__ w2l, const float* __restrict__ w2r,
    const float* __restrict__ wl2)
{
    __shared__ __align__(16) float sa[32][HID];
    int j = threadIdx.x;
    int row0 = blockIdx.x * 32;

    for (int i = j; i < 32 * (HID / 4); i += 384) {
        int r = i >> 6, c4 = i & 63;
        int row = row0 + r;
        ((float4*)sa[r])[c4] = (row < NN)
            ? ((const float4*)(g_h + (size_t)row * HID))[c4]
            : make_float4(0.f, 0.f, 0.f, 0.f);
    }
    __syncthreads();

    const float* wcol = nullptr; int slot = -1;
    if      (j < NC)     { wcol = w2l + j;          slot = j;      }
    else if (j < 2*NC)   { wcol = w2r + (j - NC);   slot = j + 7;  }
    else if (j < 3*NC)   { wcol = wl2 + (j - 2*NC); slot = j + 14; }

    if (wcol) {
        float acc[32];
#pragma unroll
        for (int r = 0; r < 32; r++) acc[r] = 0.f;
        for (int k = 0; k < HID; k += 4) {
            float w0 = wcol[(k+0)*NC], w1 = wcol[(k+1)*NC];
            float w2 = wcol[(k+2)*NC], w3 = wcol[(k+3)*NC];
#pragma unroll
            for (int r = 0; r < 32; r++) {
                float4 a = *(const float4*)&sa[r][k];
                acc[r] += a.x*w0 + a.y*w1 + a.z*w2 + a.w*w3;
            }
        }
#pragma unroll
        for (int r = 0; r < 32; r++)
            if (row0 + r < NN)
                g_prl[(size_t)(row0 + r) * PRLS + slot] = acc[r];
    } else {
        // zero pad slots (121..127, 249..255, 377..383) so gather2 float4 reads are clean
        int t2 = j - 3 * NC;           // 0..20
        int grp = t2 / 7, idx = t2 % 7;
        int slot2 = grp * 128 + NC + idx;
#pragma unroll
        for (int r = 0; r < 32; r++)
            if (row0 + r < NN)
                g_prl[(size_t)(row0 + r) * PRLS + slot2] = 0.f;
    }
}

// ---------------- gather 2 + fused final epilogue -------------------------------
// warp per node; lanes 0..30 hold 31 float4 accumulators (124 cols, pads zero)
__global__ __launch_bounds__(256) void gather2_final_kernel(
    const float* __restrict__ b2, const float* __restrict__ bl2,
    float* __restrict__ out)
{
    int t = blockIdx.x * blockDim.x + threadIdx.x;
    int n = t >> 5;
    if (n >= NN) return;
    int l = t & 31;
    int b = g_off[n], e2 = g_off[n + 1];
    float invd = 1.f / fmaxf((float)(e2 - b), 1.f);

    float4 a = make_float4(0.f, 0.f, 0.f, 0.f);
    int i = b;
    for (; i + 1 < e2; i += 2) {
        int s0 = g_adj[i], s1 = g_adj[i + 1];
        if (l < 31) {
            float4 v0 = *(const float4*)(g_prl + (size_t)s0 * PRLS + l * 4);
            float4 v1 = *(const float4*)(g_prl + (size_t)s1 * PRLS + l * 4);
            a.x += v0.x + v1.x; a.y += v0.y + v1.y;
            a.z += v0.z + v1.z; a.w += v0.w + v1.w;
        }
    }
    if (i < e2) {
        int s0 = g_adj[i];
        if (l < 31) {
            float4 v0 = *(const float4*)(g_prl + (size_t)s0 * PRLS + l * 4);
            a.x += v0.x; a.y += v0.y; a.z += v0.z; a.w += v0.w;
        }
    }

    float4 tv = make_float4(0.f, 0.f, 0.f, 0.f);
    float4 l2v = make_float4(0.f, 0.f, 0.f, 0.f);
    int c = l * 4;
    if (l < 31) {
        float4 rr = *(const float4*)(g_prl + (size_t)n * PRLS + 128 + c);
        float4 ll = *(const float4*)(g_prl + (size_t)n * PRLS + 256 + c);
        float b0 = (c + 0 < NC) ? b2[c + 0] : 0.f;
        float bb1 = (c + 1 < NC) ? b2[c + 1] : 0.f;
        float bb2 = (c + 2 < NC) ? b2[c + 2] : 0.f;
        float b3 = (c + 3 < NC) ? b2[c + 3] : 0.f;
        tv.x = a.x * invd + b0  + rr.x;
        tv.y = a.y * invd + bb1 + rr.y;
        tv.z = a.z * invd + bb2 + rr.z;
        tv.w = a.w * invd + b3  + rr.w;
        l2v.x = ll.x + ((c + 0 < NC) ? bl2[c + 0] : 0.f);
        l2v.y = ll.y + ((c + 1 < NC) ? bl2[c + 1] : 0.f);
        l2v.z = ll.z + ((c + 2 < NC) ? bl2[c + 2] : 0.f);
        l2v.w = ll.w + ((c + 3 < NC) ? bl2[c + 3] : 0.f);
    }
    // pad cols (121..123) are exactly 0 in tv (a, rr, b2 guards all zero) -> safe sumsq
    float s = tv.x * tv.x + tv.y * tv.y + tv.z * tv.z + tv.w * tv.w;
#pragma unroll
    for (int o = 16; o; o >>= 1) s += __shfl_xor_sync(0xffffffffu, s, o);
    float inv = 1.f / fmaxf(sqrtf(s), 1e-12f);

    float* orow = out + (size_t)n * NC;
    if (l < 30) {
        orow[c + 0] = tv.x * inv + l2v.x;
        orow[c + 1] = tv.y * inv + l2v.y;
        orow[c + 2] = tv.z * inv + l2v.z;
        orow[c + 3] = tv.w * inv + l2v.w;
    } else if (l == 30) {
        orow[120] = tv.x * inv + l2v.x;
    }
}

// ---------------- launcher -------------------------------------------------------
extern "C" void kernel_launch(void* const* d_in, const int* in_sizes, int n_in,
                              void* d_out, int out_size)
{
    const float* x   = (const float*)d_in[0];
    const int*   ei  = (const int*)d_in[1];
    const float* w1l = (const float*)d_in[2];
    const float* b1  = (const float*)d_in[3];
    const float* w1r = (const float*)d_in[4];
    const float* wl1 = (const float*)d_in[5];
    const float* bl1 = (const float*)d_in[6];
    const float* w2l = (const float*)d_in[7];
    const float* b2  = (const float*)d_in[8];
    const float* w2r = (const float*)d_in[9];
    const float* wl2 = (const float*)d_in[10];
    const float* bl2 = (const float*)d_in[11];
    float* out = (float*)d_out;

    zero_cnt_kernel   <<<(NN + 1023) / 1024, 1024>>>();
    pad_x_kernel      <<<(NN * XP) / 256, 256>>>(x);
    hist_kernel       <<<(NE + 255) / 256, 256>>>(ei);
    scan_kernel       <<<1, 1024>>>();
    fill_kernel       <<<(NE + 255) / 256, 256>>>(ei);
    gather1_kernel    <<<(NN * 16 + 255) / 256, 256>>>();
    gemm1_kernel      <<<(NN + 31) / 32, 256>>>(x, w1l, b1, w1r, wl1, bl1);
    gemm2_kernel      <<<(NN + 31) / 32, 384>>>(w2l, w2r, wl2);
    gather2_final_kernel<<<(NN * 32 + 255) / 256, 256>>>(b2, bl2, out);
}

// round 4
// speedup vs baseline: 1.5006x; 1.5006x over previous
#include <cuda_runtime.h>
#include <math.h>

#define NN   50000      // nodes
#define NE   800000     // edges
#define IND  50         // input dim
#define HID  256        // hidden
#define NC   121        // classes
#define XP   64         // padded x / mean row stride
#define PRLS 384        // combined [p(0..127) | r(128..255) | l2(256..383)] row stride

// ---------------- scratch (device globals) ----------------------------------
__device__ __align__(16) float g_xpad[(size_t)NN * XP];
__device__ __align__(16) float g_mean[(size_t)NN * XP];
__device__ __align__(16) float g_h   [(size_t)NN * HID];
__device__ __align__(16) float g_prl [(size_t)NN * PRLS];
__device__ int g_cnt[NN];          // dst histogram (degree)
__device__ int g_off[NN];          // CSR segment start (order-free placement)
__device__ int g_cur[NN];          // fill cursors
__device__ int g_adj[NE];          // src ids grouped by dst
__device__ int g_base;             // global allocation cursor

// ---------------- init: zero cnt/base + pad x into [NN,64] -------------------
__global__ __launch_bounds__(256) void init_kernel(const float* __restrict__ x) {
    int t = blockIdx.x * blockDim.x + threadIdx.x;
    if (t == 0) g_base = 0;
    if (t < NN) g_cnt[t] = 0;
    if (t < NN * XP) {
        int row = t >> 6, c = t & 63;
        g_xpad[t] = (c < IND) ? x[row * IND + c] : 0.f;
    }
}

// ---------------- CSR build: histogram ---------------------------------------
__global__ __launch_bounds__(256) void hist_kernel(const int* __restrict__ ei) {
    int e = blockIdx.x * blockDim.x + threadIdx.x;
    if (e < NE) atomicAdd(&g_cnt[ei[NE + e]], 1);
}

// ---------------- CSR build: order-free offsets (block scan + atomic base) ---
__global__ __launch_bounds__(1024) void offsets_kernel() {
    __shared__ int ws[32];
    __shared__ int sbase;
    int i = blockIdx.x * 1024 + threadIdx.x;
    int lane = threadIdx.x & 31, wid = threadIdx.x >> 5;
    int c = (i < NN) ? g_cnt[i] : 0;
    int v = c;
#pragma unroll
    for (int o = 1; o < 32; o <<= 1) {
        int u = __shfl_up_sync(0xffffffffu, v, o);
        if (lane >= o) v += u;
    }
    if (lane == 31) ws[wid] = v;
    __syncthreads();
    if (wid == 0) {
        int w = ws[lane];
#pragma unroll
        for (int o = 1; o < 32; o <<= 1) {
            int u = __shfl_up_sync(0xffffffffu, w, o);
            if (lane >= o) w += u;
        }
        ws[lane] = w;
    }
    __syncthreads();
    int excl = v - c + (wid ? ws[wid - 1] : 0);
    if (threadIdx.x == 1023) sbase = atomicAdd(&g_base, excl + c);
    __syncthreads();
    if (i < NN) { int o = sbase + excl; g_off[i] = o; g_cur[i] = o; }
}

// ---------------- CSR build: fill adjacency -----------------------------------
__global__ __launch_bounds__(256) void fill_kernel(const int* __restrict__ ei) {
    int e = blockIdx.x * blockDim.x + threadIdx.x;
    if (e >= NE) return;
    int pos = atomicAdd(&g_cur[ei[NE + e]], 1);
    g_adj[pos] = ei[e];
}

// ---------------- gather 1: mean of x over in-neighbors ------------------------
// half-warp (16 lanes) per node; lanes 0..12 hold 13 float4 accumulators
__global__ __launch_bounds__(256) void gather1_kernel() {
    int t = blockIdx.x * blockDim.x + threadIdx.x;
    int n = t >> 4;
    if (n >= NN) return;
    int l = t & 15;
    int b = g_off[n], cnt = g_cnt[n], e2 = b + cnt;
    float inv = 1.f / fmaxf((float)cnt, 1.f);
    float4 a = make_float4(0.f, 0.f, 0.f, 0.f);
    int i = b;
    for (; i + 1 < e2; i += 2) {
        int s0 = g_adj[i], s1 = g_adj[i + 1];
        if (l < 13) {
            float4 v0 = *(const float4*)(g_xpad + (size_t)s0 * XP + l * 4);
            float4 v1 = *(const float4*)(g_xpad + (size_t)s1 * XP + l * 4);
            a.x += v0.x + v1.x; a.y += v0.y + v1.y;
            a.z += v0.z + v1.z; a.w += v0.w + v1.w;
        }
    }
    if (i < e2) {
        int s0 = g_adj[i];
        if (l < 13) {
            float4 v0 = *(const float4*)(g_xpad + (size_t)s0 * XP + l * 4);
            a.x += v0.x; a.y += v0.y; a.z += v0.z; a.w += v0.w;
        }
    }
    if (l < 13) {
        a.x *= inv; a.y *= inv; a.z *= inv; a.w *= inv;
        *(float4*)(g_mean + (size_t)n * XP + l * 4) = a;
    }
}

// ---------------- layer-1 fused GEMM + L2-normalize + ELU ----------------------
// 256 threads: half = t>>7 owns 16 rows, col = t&127 owns cols {col, col+128}
__global__ __launch_bounds__(256, 2) void gemm1_kernel(
    const float* __restrict__ x,
    const float* __restrict__ w1l, const float* __restrict__ b1,
    const float* __restrict__ w1r,
    const float* __restrict__ wl1, const float* __restrict__ bl1)
{
    __shared__ __align__(16) float sm[32][64];
    __shared__ __align__(16) float sx[32][64];
    __shared__ float spart[2][16][4];

    int j = threadIdx.x;
    int col = j & 127, half = j >> 7;
    int c0 = col, c1 = col + 128;
    int r0 = half * 16;
    int row0 = blockIdx.x * 32;

    for (int i = j; i < 32 * 52; i += 256) {
        int r = i / 52, c = i % 52;
        int row = row0 + r;
        bool ok = (row < NN);
        sm[r][c] = ok ? g_mean[(size_t)row * XP + c] : 0.f;
        sx[r][c] = (ok && c < IND) ? x[(size_t)row * IND + c] : 0.f;
    }
    __syncthreads();

    float a0[16], l0[16], a1[16], l1[16];
    float bj0 = b1[c0], blj0 = bl1[c0];
    float bj1 = b1[c1], blj1 = bl1[c1];
#pragma unroll
    for (int r = 0; r < 16; r++) { a0[r] = bj0; l0[r] = blj0; a1[r] = bj1; l1[r] = blj1; }

    for (int k = 0; k < 48; k += 4) {
        float wa0 = w1l[(k+0)*HID + c0], wa1 = w1l[(k+1)*HID + c0];
        float wa2 = w1l[(k+2)*HID + c0], wa3 = w1l[(k+3)*HID + c0];
        float wA0 = w1l[(k+0)*HID + c1], wA1 = w1l[(k+1)*HID + c1];
        float wA2 = w1l[(k+2)*HID + c1], wA3 = w1l[(k+3)*HID + c1];
        float wb0 = w1r[(k+0)*HID + c0], wb1 = w1r[(k+1)*HID + c0];
        float wb2 = w1r[(k+2)*HID + c0], wb3 = w1r[(k+3)*HID + c0];
        float wB0 = w1r[(k+0)*HID + c1], wB1 = w1r[(k+1)*HID + c1];
        float wB2 = w1r[(k+2)*HID + c1], wB3 = w1r[(k+3)*HID + c1];
        float wc0 = wl1[(k+0)*HID + c0], wc1 = wl1[(k+1)*HID + c0];
        float wc2 = wl1[(k+2)*HID + c0], wc3 = wl1[(k+3)*HID + c0];
        float wC0 = wl1[(k+0)*HID + c1], wC1 = wl1[(k+1)*HID + c1];
        float wC2 = wl1[(k+2)*HID + c1], wC3 = wl1[(k+3)*HID + c1];
#pragma unroll
        for (int r = 0; r < 16; r++) {
            float4 m  = *(const float4*)&sm[r0 + r][k];
            float4 xv = *(const float4*)&sx[r0 + r][k];
            a0[r] += m.x*wa0 + m.y*wa1 + m.z*wa2 + m.w*wa3
                   + xv.x*wb0 + xv.y*wb1 + xv.z*wb2 + xv.w*wb3;
            l0[r] += xv.x*wc0 + xv.y*wc1 + xv.z*wc2 + xv.w*wc3;
            a1[r] += m.x*wA0 + m.y*wA1 + m.z*wA2 + m.w*wA3
                   + xv.x*wB0 + xv.y*wB1 + xv.z*wB2 + xv.w*wB3;
            l1[r] += xv.x*wC0 + xv.y*wC1 + xv.z*wC2 + xv.w*wC3;
        }
    }
    for (int k = 48; k < 50; k++) {
        float wa = w1l[k*HID + c0], wA = w1l[k*HID + c1];
        float wb = w1r[k*HID + c0], wB = w1r[k*HID + c1];
        float wc = wl1[k*HID + c0], wC = wl1[k*HID + c1];
#pragma unroll
        for (int r = 0; r < 16; r++) {
            float mm = sm[r0 + r][k], xx = sx[r0 + r][k];
            a0[r] += mm * wa + xx * wb;  l0[r] += xx * wc;
            a1[r] += mm * wA + xx * wB;  l1[r] += xx * wC;
        }
    }

    int lane = j & 31, wg = (j >> 5) & 3;   // warp within row-half group
#pragma unroll
    for (int r = 0; r < 16; r++) {
        float v = a0[r]*a0[r] + a1[r]*a1[r];
#pragma unroll
        for (int o = 16; o; o >>= 1) v += __shfl_xor_sync(0xffffffffu, v, o);
        if (lane == 0) spart[half][r][wg] = v;
    }
    __syncthreads();
#pragma unroll
    for (int r = 0; r < 16; r++) {
        int row = row0 + r0 + r;
        if (row >= NN) continue;
        float s = spart[half][r][0] + spart[half][r][1]
                + spart[half][r][2] + spart[half][r][3];
        float inv = 1.f / fmaxf(sqrtf(s), 1e-12f);
        float z0 = a0[r] * inv + l0[r];
        float z1 = a1[r] * inv + l1[r];
        g_h[(size_t)row * HID + c0] = (z0 > 0.f) ? z0 : expm1f(z0);
        g_h[(size_t)row * HID + c1] = (z1 > 0.f) ? z1 : expm1f(z1);
    }
}

// ---------------- layer-2 GEMM: [p | r | l2] = h @ [w2_l | w2_r | wl2] ---------
// 192 threads, cols {t, t+192}, 32 rows per block
__global__ __launch_bounds__(192, 3) void gemm2_kernel(
    const float* __restrict__ w2l, const float* __restrict__ w2r,
    const float* __restrict__ wl2)
{
    __shared__ __align__(16) float sa[32][HID];
    int t = threadIdx.x;
    int row0 = blockIdx.x * 32;

    for (int i = t; i < 32 * (HID / 4); i += 192) {
        int r = i >> 6, c4 = i & 63;
        int row = row0 + r;
        ((float4*)sa[r])[c4] = (row < NN)
            ? ((const float4*)(g_h + (size_t)row * HID))[c4]
            : make_float4(0.f, 0.f, 0.f, 0.f);
    }
    __syncthreads();

    int s0 = t, s1 = t + 192;                 // slots in 0..383
    int seg0 = s0 >> 7, idx0 = s0 & 127;
    int seg1 = s1 >> 7, idx1 = s1 & 127;
    bool v0 = idx0 < NC, v1 = idx1 < NC;
    const float* m0 = (seg0 == 0) ? w2l : (seg0 == 1) ? w2r : wl2;
    const float* m1 = (seg1 == 0) ? w2l : (seg1 == 1) ? w2r : wl2;
    const float* w0p = m0 + (v0 ? idx0 : 0);
    const float* w1p = m1 + (v1 ? idx1 : 0);

    float acc0[32], acc1[32];
#pragma unroll
    for (int r = 0; r < 32; r++) { acc0[r] = 0.f; acc1[r] = 0.f; }

    for (int k = 0; k < HID; k += 4) {
        float w00 = w0p[(k+0)*NC], w01 = w0p[(k+1)*NC];
        float w02 = w0p[(k+2)*NC], w03 = w0p[(k+3)*NC];
        float w10 = w1p[(k+0)*NC], w11 = w1p[(k+1)*NC];
        float w12 = w1p[(k+2)*NC], w13 = w1p[(k+3)*NC];
#pragma unroll
        for (int r = 0; r < 32; r++) {
            float4 a = *(const float4*)&sa[r][k];
            acc0[r] += a.x*w00 + a.y*w01 + a.z*w02 + a.w*w03;
            acc1[r] += a.x*w10 + a.y*w11 + a.z*w12 + a.w*w13;
        }
    }
#pragma unroll
    for (int r = 0; r < 32; r++) {
        int row = row0 + r;
        if (row >= NN) break;
        g_prl[(size_t)row * PRLS + s0] = v0 ? acc0[r] : 0.f;
        g_prl[(size_t)row * PRLS + s1] = v1 ? acc1[r] : 0.f;
    }
}

// ---------------- gather 2 + fused final epilogue -------------------------------
// warp per node; lanes 0..30 hold 31 float4 accumulators over p (124 cols)
__global__ __launch_bounds__(256) void gather2_final_kernel(
    const float* __restrict__ b2, const float* __restrict__ bl2,
    float* __restrict__ out)
{
    int t = blockIdx.x * blockDim.x + threadIdx.x;
    int n = t >> 5;
    if (n >= NN) return;
    int l = t & 31;
    int b = g_off[n], cnt = g_cnt[n], e2 = b + cnt;
    float invd = 1.f / fmaxf((float)cnt, 1.f);

    float4 a = make_float4(0.f, 0.f, 0.f, 0.f);
    int i = b;
    for (; i + 1 < e2; i += 2) {
        int src0 = g_adj[i], src1 = g_adj[i + 1];
        if (l < 31) {
            float4 v0 = *(const float4*)(g_prl + (size_t)src0 * PRLS + l * 4);
            float4 v1 = *(const float4*)(g_prl + (size_t)src1 * PRLS + l * 4);
            a.x += v0.x + v1.x; a.y += v0.y + v1.y;
            a.z += v0.z + v1.z; a.w += v0.w + v1.w;
        }
    }
    if (i < e2) {
        int src0 = g_adj[i];
        if (l < 31) {
            float4 v0 = *(const float4*)(g_prl + (size_t)src0 * PRLS + l * 4);
            a.x += v0.x; a.y += v0.y; a.z += v0.z; a.w += v0.w;
        }
    }

    float4 tv = make_float4(0.f, 0.f, 0.f, 0.f);
    float4 l2v = make_float4(0.f, 0.f, 0.f, 0.f);
    int c = l * 4;
    if (l < 31) {
        float4 rr = *(const float4*)(g_prl + (size_t)n * PRLS + 128 + c);
        float4 ll = *(const float4*)(g_prl + (size_t)n * PRLS + 256 + c);
        float b0  = (c + 0 < NC) ? b2[c + 0] : 0.f;
        float bb1 = (c + 1 < NC) ? b2[c + 1] : 0.f;
        float bb2 = (c + 2 < NC) ? b2[c + 2] : 0.f;
        float b3  = (c + 3 < NC) ? b2[c + 3] : 0.f;
        tv.x = a.x * invd + b0  + rr.x;
        tv.y = a.y * invd + bb1 + rr.y;
        tv.z = a.z * invd + bb2 + rr.z;
        tv.w = a.w * invd + b3  + rr.w;
        l2v.x = ll.x + ((c + 0 < NC) ? bl2[c + 0] : 0.f);
        l2v.y = ll.y + ((c + 1 < NC) ? bl2[c + 1] : 0.f);
        l2v.z = ll.z + ((c + 2 < NC) ? bl2[c + 2] : 0.f);
        l2v.w = ll.w + ((c + 3 < NC) ? bl2[c + 3] : 0.f);
    }
    float s = tv.x*tv.x + tv.y*tv.y + tv.z*tv.z + tv.w*tv.w;
#pragma unroll
    for (int o = 16; o; o >>= 1) s += __shfl_xor_sync(0xffffffffu, s, o);
    float inv = 1.f / fmaxf(sqrtf(s), 1e-12f);

    float* orow = out + (size_t)n * NC;
    if (l < 30) {
        orow[c + 0] = tv.x * inv + l2v.x;
        orow[c + 1] = tv.y * inv + l2v.y;
        orow[c + 2] = tv.z * inv + l2v.z;
        orow[c + 3] = tv.w * inv + l2v.w;
    } else if (l == 30) {
        orow[120] = tv.x * inv + l2v.x;
    }
}

// ---------------- launcher --------------------------------------------------------
extern "C" void kernel_launch(void* const* d_in, const int* in_sizes, int n_in,
                              void* d_out, int out_size)
{
    const float* x   = (const float*)d_in[0];
    const int*   ei  = (const int*)d_in[1];
    const float* w1l = (const float*)d_in[2];
    const float* b1  = (const float*)d_in[3];
    const float* w1r = (const float*)d_in[4];
    const float* wl1 = (const float*)d_in[5];
    const float* bl1 = (const float*)d_in[6];
    const float* w2l = (const float*)d_in[7];
    const float* b2  = (const float*)d_in[8];
    const float* w2r = (const float*)d_in[9];
    const float* wl2 = (const float*)d_in[10];
    const float* bl2 = (const float*)d_in[11];
    float* out = (float*)d_out;

    init_kernel        <<<(NN * XP + 255) / 256, 256>>>(x);
    hist_kernel        <<<(NE + 255) / 256, 256>>>(ei);
    offsets_kernel     <<<(NN + 1023) / 1024, 1024>>>();
    fill_kernel        <<<(NE + 255) / 256, 256>>>(ei);
    gather1_kernel     <<<(NN * 16 + 255) / 256, 256>>>();
    gemm1_kernel       <<<(NN + 31) / 32, 256>>>(x, w1l, b1, w1r, wl1, bl1);
    gemm2_kernel       <<<(NN + 31) / 32, 192>>>(w2l, w2r, wl2);
    gather2_final_kernel<<<(NN * 32 + 255) / 256, 256>>>(b2, bl2, out);
}